// round 9
// baseline (speedup 1.0000x reference)
#include <cuda_runtime.h>
#include <cuda_fp16.h>
#include <cuda_fp8.h>
#include <stdint.h>
#include <math.h>

// ---------------------------------------------------------------------------
// Static scratch (no runtime allocation allowed).
//   g_s : per-(node,head) exp-sum accumulator (float), 16B-aligned rows (H=4)
//   g_q8/g_k8 : e4m3 copies of Q2/K2 (row = H*D bytes = 128B = 1 line)
//   scalar params precomputed once in prep
// ---------------------------------------------------------------------------
#define MAX_S   (4 * 1024 * 1024)
#define MAX_NHD (8 * 1024 * 1024)
#define MAX_HB  64
__device__ __align__(16) float g_s[MAX_S];
__device__ unsigned char g_q8[MAX_NHD];
__device__ unsigned char g_k8[MAX_NHD];
__device__ float         g_bs;          // beta / sqrt(D)
__device__ float         g_ba[MAX_HB];  // beta * a[h]
__device__ float         g_coef;        // lam / beta

__device__ __forceinline__ float softplus_f(float x) {
    return log1pf(expf(x));
}

__device__ __forceinline__ __half2 fp8x2_to_h2(unsigned short s) {
    union { __half2_raw r; __half2 h; } cvt;
    cvt.r = __nv_cvt_fp8x2_to_halfraw2((__nv_fp8x2_storage_t)s, __NV_E4M3);
    return cvt.h;
}

// ---------------------------------------------------------------------------
// Kernel A (fused): zero g_s + out, convert Q/K f32 -> e4m3, precompute
// scalar params (thread 0).
// ---------------------------------------------------------------------------
__global__ void prep_kernel(const float* __restrict__ Q,
                            const float* __restrict__ K,
                            const float* __restrict__ a,
                            const float* __restrict__ lam_raw,
                            const float* __restrict__ beta_raw,
                            float* __restrict__ out,
                            int out_size, int s_count, int total4,
                            int H, int D) {
    int i = blockIdx.x * blockDim.x + threadIdx.x;
    if (i == 0) {
        float beta = fminf(softplus_f(beta_raw[0]), 10.0f);
        float lam  = softplus_f(lam_raw[0]);
        g_bs   = beta * rsqrtf((float)D);
        g_coef = lam / beta;
        int hb = H < MAX_HB ? H : MAX_HB;
        for (int h = 0; h < hb; h++) g_ba[h] = beta * a[h];
    }
    if (i < s_count) g_s[i] = 0.0f;
    if (i < out_size) out[i] = 0.0f;
    if (i >= total4) return;
    float4 q = reinterpret_cast<const float4*>(Q)[i];
    float4 k = reinterpret_cast<const float4*>(K)[i];
    unsigned int qp =
        (unsigned int)__nv_cvt_float2_to_fp8x2(make_float2(q.x, q.y), __NV_SATFINITE, __NV_E4M3) |
        ((unsigned int)__nv_cvt_float2_to_fp8x2(make_float2(q.z, q.w), __NV_SATFINITE, __NV_E4M3) << 16);
    unsigned int kp =
        (unsigned int)__nv_cvt_float2_to_fp8x2(make_float2(k.x, k.y), __NV_SATFINITE, __NV_E4M3) |
        ((unsigned int)__nv_cvt_float2_to_fp8x2(make_float2(k.z, k.w), __NV_SATFINITE, __NV_E4M3) << 16);
    reinterpret_cast<unsigned int*>(g_q8)[i] = qp;
    reinterpret_cast<unsigned int*>(g_k8)[i] = kp;
}

// ---------------------------------------------------------------------------
// Kernel B (H=4, D=32, fp8): 32 edges per warp, 8 lanes per edge.
// Lane l: sub = l>>3 is the edge slot within a pass, lw8 = l&7 covers 16B of
// the 128B row (LDG.128). All 32 gather pairs (64 lines) issued in the
// prologue. Reduction: pair shfl -> heads on even lanes; 3 more shfls pack
// all 4 heads into lane lw8==0, which issues ONE red.global.add.v4.f32
// (16B vector reduction) per edge: 1.6M LTS atomic ops instead of 6.4M.
// ---------------------------------------------------------------------------
__global__ void __launch_bounds__(256) edge_kernel_32(const int* __restrict__ c,
                                                      const int* __restrict__ u,
                                                      int E) {
    int warp = (blockIdx.x * blockDim.x + threadIdx.x) >> 5;
    int lane = threadIdx.x & 31;
    int sub = lane >> 3;   // edge slot within a pass (0..3)
    int lw8 = lane & 7;    // lane within edge

    int base = warp * 32;
    if (base >= E) return;

    int idx = base + lane;
    if (idx >= E) idx = E - 1;      // clamp; masked at the RED
    int v_c = c[idx];
    int v_u = u[idx];

    // Prologue: issue all 32 gather pairs (16 LDG.128 per lane, 64 lines/warp)
    uint4 qv[8], kv[8];
    int   cis[8];
#pragma unroll
    for (int p = 0; p < 8; p++) {
        int eoff = p * 4 + sub;
        int ci = __shfl_sync(0xffffffffu, v_c, eoff);
        int ui = __shfl_sync(0xffffffffu, v_u, eoff);
        cis[p] = ci;
        qv[p] = reinterpret_cast<const uint4*>(g_q8 + (size_t)ci * 128)[lw8];
        kv[p] = reinterpret_cast<const uint4*>(g_k8 + (size_t)ui * 128)[lw8];
    }

    float bs = g_bs;
    int h = lw8 >> 1;
    float bah = g_ba[h];

#pragma unroll
    for (int p = 0; p < 8; p++) {
        const unsigned int* qw = reinterpret_cast<const unsigned int*>(&qv[p]);
        const unsigned int* kw = reinterpret_cast<const unsigned int*>(&kv[p]);
        __half2 acc = __float2half2_rn(0.0f);
#pragma unroll
        for (int w = 0; w < 4; w++) {
            acc = __hfma2(fp8x2_to_h2((unsigned short)(qw[w] & 0xffff)),
                          fp8x2_to_h2((unsigned short)(kw[w] & 0xffff)), acc);
            acc = __hfma2(fp8x2_to_h2((unsigned short)(qw[w] >> 16)),
                          fp8x2_to_h2((unsigned short)(kw[w] >> 16)), acc);
        }
        float fa = __low2float(acc) + __high2float(acc);
        fa += __shfl_xor_sync(0xffffffffu, fa, 1);   // pair covers one head

        // exp on even lanes (head value holders); odd lanes compute garbage
        float ev = __expf(fmaf(fa, bs, bah));

        // pack heads: lane0 gets {h0,h1,h2,h3} of its 8-lane group
        float e1 = __shfl_xor_sync(0xffffffffu, ev, 2);  // lane0 <- h1
        float e2 = __shfl_xor_sync(0xffffffffu, ev, 4);  // lane0 <- h2
        float e3 = __shfl_xor_sync(0xffffffffu, e1, 4);  // lane0 <- h3

        int eoff = p * 4 + sub;
        if (lw8 == 0 && (base + eoff) < E) {
            float* dst = &g_s[(size_t)cis[p] * 4];
            asm volatile("red.global.add.v4.f32 [%0], {%1, %2, %3, %4};"
                         :: "l"(dst), "f"(ev), "f"(e1), "f"(e2), "f"(e3)
                         : "memory");
        }
    }
}

// Generic fallback (any H, D) — f32 path, one thread per (edge, head)
__global__ void edge_kernel_g(const float* __restrict__ Q,
                              const float* __restrict__ K,
                              const float* __restrict__ a,
                              const float* __restrict__ beta_raw,
                              const int* __restrict__ c,
                              const int* __restrict__ u,
                              int E, int H, int D) {
    long long tid = (long long)blockIdx.x * blockDim.x + threadIdx.x;
    long long total = (long long)E * H;
    if (tid >= total) return;
    int e = (int)(tid / H);
    int h = (int)(tid % H);

    int ci = c[e];
    int ui = u[e];

    const float* q = Q + ((size_t)ci * H + h) * D;
    const float* k = K + ((size_t)ui * H + h) * D;
    float acc = 0.0f;
    for (int d = 0; d < D; d++) acc = fmaf(q[d], k[d], acc);

    float beta = fminf(softplus_f(beta_raw[0]), 10.0f);
    float ell = acc * rsqrtf((float)D) + a[h];
    atomicAdd(&g_s[(size_t)ci * H + h], __expf(beta * ell));
}

// ---------------------------------------------------------------------------
// Kernel C: per-node log + per-graph reduce via block-local smem, then one
// global atomic per (graph,head) per block.
// ---------------------------------------------------------------------------
#define MAX_GH 4096
__global__ void node_kernel_sm(const int* __restrict__ batch,
                               float* __restrict__ out,
                               int N, int H, int gh) {
    __shared__ float sred[MAX_GH];
    for (int i = threadIdx.x; i < gh; i += blockDim.x) sred[i] = 0.0f;
    __syncthreads();

    if (H == 4) {
        for (int n = blockIdx.x * blockDim.x + threadIdx.x; n < N;
             n += gridDim.x * blockDim.x) {
            float4 sv = reinterpret_cast<const float4*>(g_s)[n];
            int g = batch[n];
            float v0 = sv.x > 0.0f ? logf(sv.x) : 0.0f;
            float v1 = sv.y > 0.0f ? logf(sv.y) : 0.0f;
            float v2 = sv.z > 0.0f ? logf(sv.z) : 0.0f;
            float v3 = sv.w > 0.0f ? logf(sv.w) : 0.0f;
            atomicAdd(&sred[g * 4 + 0], v0);
            atomicAdd(&sred[g * 4 + 1], v1);
            atomicAdd(&sred[g * 4 + 2], v2);
            atomicAdd(&sred[g * 4 + 3], v3);
        }
    } else {
        for (int n = blockIdx.x * blockDim.x + threadIdx.x; n < N;
             n += gridDim.x * blockDim.x) {
            int g = batch[n];
            for (int h = 0; h < H; h++) {
                float s = g_s[(size_t)n * H + h];
                float v = s > 0.0f ? logf(s) : 0.0f;
                atomicAdd(&sred[g * H + h], v);
            }
        }
    }
    __syncthreads();
    float coef = g_coef;
    for (int i = threadIdx.x; i < gh; i += blockDim.x) {
        float v = sred[i];
        if (v != 0.0f) atomicAdd(&out[i], coef * v);
    }
}

// Fallback: direct global atomics (only if out_size > MAX_GH)
__global__ void node_kernel_g(const int* __restrict__ batch,
                              float* __restrict__ out,
                              int N, int H) {
    int n = blockIdx.x * blockDim.x + threadIdx.x;
    if (n >= N) return;
    float coef = g_coef;
    int g = batch[n];
    for (int h = 0; h < H; h++) {
        float s = g_s[(size_t)n * H + h];
        float v = s > 0.0f ? logf(s) : 0.0f;
        atomicAdd(&out[g * H + h], coef * v);
    }
}

// ---------------------------------------------------------------------------
// Launch.  Inputs (metadata order):
//   0: G [4,4] f32 (unused)   1: Q2 [N,H,D] f32   2: K2 [N,H,D] f32
//   3: a_2 [H] f32   4: lambda_2_raw [1] f32   5: beta_2_raw [1] f32
//   6: c_2 [E] i32   7: u_2 [E] i32   8: batch [N] i32
// Output: [num_graphs, H] f32
// ---------------------------------------------------------------------------
extern "C" void kernel_launch(void* const* d_in, const int* in_sizes, int n_in,
                              void* d_out, int out_size) {
    const float* Q        = (const float*)d_in[1];
    const float* K        = (const float*)d_in[2];
    const float* a        = (const float*)d_in[3];
    const float* lam_raw  = (const float*)d_in[4];
    const float* beta_raw = (const float*)d_in[5];
    const int*   c        = (const int*)d_in[6];
    const int*   u        = (const int*)d_in[7];
    const int*   batch    = (const int*)d_in[8];
    float*       out      = (float*)d_out;

    int H = in_sizes[3];
    int E = in_sizes[6];
    int N = in_sizes[8];
    long long nhd = in_sizes[1];
    int D = (int)(nhd / ((long long)N * H));

    int s_count = N * H;
    if (s_count > MAX_S) return;

    const int TB = 256;
    bool fast = (H == 4 && D == 32 && nhd <= MAX_NHD && (nhd % 4) == 0);

    if (fast) {
        int total4 = (int)(nhd / 4);
        int work = total4;
        if (s_count > work) work = s_count;
        if (out_size > work) work = out_size;
        prep_kernel<<<(work + TB - 1) / TB, TB>>>(Q, K, a, lam_raw, beta_raw,
                                                  out, out_size, s_count, total4, H, D);

        // 32 edges per warp
        long long warps = (E + 31) / 32;
        long long threads = warps * 32;
        int blocks = (int)((threads + TB - 1) / TB);
        edge_kernel_32<<<blocks, TB>>>(c, u, E);
    } else {
        prep_kernel<<<((s_count > out_size ? s_count : out_size) + TB - 1) / TB, TB>>>(
            Q, K, a, lam_raw, beta_raw, out, out_size, s_count, 0, H, D);
        long long total = (long long)E * H;
        edge_kernel_g<<<(int)((total + TB - 1) / TB), TB>>>(Q, K, a, beta_raw, c, u, E, H, D);
    }

    if (out_size <= MAX_GH) {
        int blocks = (N + TB - 1) / TB;
        if (blocks > 120) blocks = 120;
        node_kernel_sm<<<blocks, TB>>>(batch, out, N, H, out_size);
    } else {
        node_kernel_g<<<(N + TB - 1) / TB, TB>>>(batch, out, N, H);
    }
}

// round 10
// speedup vs baseline: 1.0184x; 1.0184x over previous
#include <cuda_runtime.h>
#include <cuda_fp16.h>
#include <cuda_fp8.h>
#include <stdint.h>
#include <math.h>

// ---------------------------------------------------------------------------
// Static scratch (no runtime allocation allowed).
//   g_s : per-(node,head) exp-sum accumulator (float), 16B-aligned rows (H=4)
//   g_q8/g_k8 : e4m3 copies of Q2/K2 (row = H*D bytes = 128B = 1 line)
//   scalar params precomputed once in prep
// ---------------------------------------------------------------------------
#define MAX_S   (4 * 1024 * 1024)
#define MAX_NHD (8 * 1024 * 1024)
#define MAX_HB  64
__device__ __align__(16) float g_s[MAX_S];
__device__ unsigned char g_q8[MAX_NHD];
__device__ unsigned char g_k8[MAX_NHD];
__device__ float         g_bs;          // beta / sqrt(D)
__device__ float         g_ba[MAX_HB];  // beta * a[h]
__device__ float         g_coef;        // lam / beta

__device__ __forceinline__ float softplus_f(float x) {
    return log1pf(expf(x));
}

__device__ __forceinline__ __half2 fp8x2_to_h2(unsigned short s) {
    union { __half2_raw r; __half2 h; } cvt;
    cvt.r = __nv_cvt_fp8x2_to_halfraw2((__nv_fp8x2_storage_t)s, __NV_E4M3);
    return cvt.h;
}

// ---------------------------------------------------------------------------
// Kernel A (fused): zero g_s + out, convert Q/K f32 -> e4m3, precompute
// scalar params (thread 0).
// ---------------------------------------------------------------------------
__global__ void prep_kernel(const float* __restrict__ Q,
                            const float* __restrict__ K,
                            const float* __restrict__ a,
                            const float* __restrict__ lam_raw,
                            const float* __restrict__ beta_raw,
                            float* __restrict__ out,
                            int out_size, int s_count, int total4,
                            int H, int D) {
    int i = blockIdx.x * blockDim.x + threadIdx.x;
    if (i == 0) {
        float beta = fminf(softplus_f(beta_raw[0]), 10.0f);
        float lam  = softplus_f(lam_raw[0]);
        g_bs   = beta * rsqrtf((float)D);
        g_coef = lam / beta;
        int hb = H < MAX_HB ? H : MAX_HB;
        for (int h = 0; h < hb; h++) g_ba[h] = beta * a[h];
    }
    if (i < s_count) g_s[i] = 0.0f;
    if (i < out_size) out[i] = 0.0f;
    if (i >= total4) return;
    float4 q = reinterpret_cast<const float4*>(Q)[i];
    float4 k = reinterpret_cast<const float4*>(K)[i];
    unsigned int qp =
        (unsigned int)__nv_cvt_float2_to_fp8x2(make_float2(q.x, q.y), __NV_SATFINITE, __NV_E4M3) |
        ((unsigned int)__nv_cvt_float2_to_fp8x2(make_float2(q.z, q.w), __NV_SATFINITE, __NV_E4M3) << 16);
    unsigned int kp =
        (unsigned int)__nv_cvt_float2_to_fp8x2(make_float2(k.x, k.y), __NV_SATFINITE, __NV_E4M3) |
        ((unsigned int)__nv_cvt_float2_to_fp8x2(make_float2(k.z, k.w), __NV_SATFINITE, __NV_E4M3) << 16);
    reinterpret_cast<unsigned int*>(g_q8)[i] = qp;
    reinterpret_cast<unsigned int*>(g_k8)[i] = kp;
}

// ---------------------------------------------------------------------------
// Kernel B (H=4, D=32, fp8): 16 edges per warp, 8 lanes per edge (R8 geometry),
// with ONE red.global.add.v4.f32 per edge instead of 4 scalar atomics:
// 1.6M LTS RMW ops instead of 6.4M, ~4x less internal L2 RMW traffic.
// ---------------------------------------------------------------------------
__global__ void __launch_bounds__(256) edge_kernel_16(const int* __restrict__ c,
                                                      const int* __restrict__ u,
                                                      int E) {
    int warp = (blockIdx.x * blockDim.x + threadIdx.x) >> 5;
    int lane = threadIdx.x & 31;
    int sub = lane >> 3;   // edge slot within a pass (0..3)
    int lw8 = lane & 7;    // lane within edge

    int base = warp * 16;
    if (base >= E) return;

    // lanes 0-15 load c[base+lane], lanes 16-31 load u[base+lane-16]
    int j = lane & 15;
    int idx = base + j;
    if (idx >= E) idx = E - 1;   // clamp; masked at the RED
    int v = (lane < 16) ? c[idx] : u[idx];

    // Prologue: issue all 16 gather pairs (8 LDG.128 per lane, 32 lines/warp)
    uint4 qv[4], kv[4];
    int   cis[4];
    bool  act[4];
#pragma unroll
    for (int p = 0; p < 4; p++) {
        int eoff = p * 4 + sub;
        act[p] = (base + eoff < E);
        int ci = __shfl_sync(0xffffffffu, v, eoff);
        int ui = __shfl_sync(0xffffffffu, v, 16 + eoff);
        cis[p] = ci;
        qv[p] = reinterpret_cast<const uint4*>(g_q8 + (size_t)ci * 128)[lw8];
        kv[p] = reinterpret_cast<const uint4*>(g_k8 + (size_t)ui * 128)[lw8];
    }

    float bs = g_bs;
    int h = lw8 >> 1;
    float bah = g_ba[h];

#pragma unroll
    for (int p = 0; p < 4; p++) {
        const unsigned int* qw = reinterpret_cast<const unsigned int*>(&qv[p]);
        const unsigned int* kw = reinterpret_cast<const unsigned int*>(&kv[p]);
        __half2 acc = __float2half2_rn(0.0f);
#pragma unroll
        for (int w = 0; w < 4; w++) {
            acc = __hfma2(fp8x2_to_h2((unsigned short)(qw[w] & 0xffff)),
                          fp8x2_to_h2((unsigned short)(kw[w] & 0xffff)), acc);
            acc = __hfma2(fp8x2_to_h2((unsigned short)(qw[w] >> 16)),
                          fp8x2_to_h2((unsigned short)(kw[w] >> 16)), acc);
        }
        float fa = __low2float(acc) + __high2float(acc);
        fa += __shfl_xor_sync(0xffffffffu, fa, 1);   // pair covers one head

        // exp on head-holder (even) lanes; odd lanes produce garbage (unused)
        float ev = __expf(fmaf(fa, bs, bah));

        // pack heads into lane lw8==0: ev@lanes{0,2,4,6} = h0..h3
        float e1 = __shfl_xor_sync(0xffffffffu, ev, 2);  // lane0 <- h1
        float e2 = __shfl_xor_sync(0xffffffffu, ev, 4);  // lane0 <- h2
        float e3 = __shfl_xor_sync(0xffffffffu, e1, 4);  // lane0 <- h3

        if (act[p] && lw8 == 0) {
            float* dst = &g_s[(size_t)cis[p] * 4];
            asm volatile("red.global.add.v4.f32 [%0], {%1, %2, %3, %4};"
                         :: "l"(dst), "f"(ev), "f"(e1), "f"(e2), "f"(e3)
                         : "memory");
        }
    }
}

// Generic fallback (any H, D) — f32 path, one thread per (edge, head)
__global__ void edge_kernel_g(const float* __restrict__ Q,
                              const float* __restrict__ K,
                              const float* __restrict__ a,
                              const float* __restrict__ beta_raw,
                              const int* __restrict__ c,
                              const int* __restrict__ u,
                              int E, int H, int D) {
    long long tid = (long long)blockIdx.x * blockDim.x + threadIdx.x;
    long long total = (long long)E * H;
    if (tid >= total) return;
    int e = (int)(tid / H);
    int h = (int)(tid % H);

    int ci = c[e];
    int ui = u[e];

    const float* q = Q + ((size_t)ci * H + h) * D;
    const float* k = K + ((size_t)ui * H + h) * D;
    float acc = 0.0f;
    for (int d = 0; d < D; d++) acc = fmaf(q[d], k[d], acc);

    float beta = fminf(softplus_f(beta_raw[0]), 10.0f);
    float ell = acc * rsqrtf((float)D) + a[h];
    atomicAdd(&g_s[(size_t)ci * H + h], __expf(beta * ell));
}

// ---------------------------------------------------------------------------
// Kernel C: per-node log + per-graph reduce via block-local smem, then one
// global atomic per (graph,head) per block.
// ---------------------------------------------------------------------------
#define MAX_GH 4096
__global__ void node_kernel_sm(const int* __restrict__ batch,
                               float* __restrict__ out,
                               int N, int H, int gh) {
    __shared__ float sred[MAX_GH];
    for (int i = threadIdx.x; i < gh; i += blockDim.x) sred[i] = 0.0f;
    __syncthreads();

    if (H == 4) {
        for (int n = blockIdx.x * blockDim.x + threadIdx.x; n < N;
             n += gridDim.x * blockDim.x) {
            float4 sv = reinterpret_cast<const float4*>(g_s)[n];
            int g = batch[n];
            float v0 = sv.x > 0.0f ? logf(sv.x) : 0.0f;
            float v1 = sv.y > 0.0f ? logf(sv.y) : 0.0f;
            float v2 = sv.z > 0.0f ? logf(sv.z) : 0.0f;
            float v3 = sv.w > 0.0f ? logf(sv.w) : 0.0f;
            atomicAdd(&sred[g * 4 + 0], v0);
            atomicAdd(&sred[g * 4 + 1], v1);
            atomicAdd(&sred[g * 4 + 2], v2);
            atomicAdd(&sred[g * 4 + 3], v3);
        }
    } else {
        for (int n = blockIdx.x * blockDim.x + threadIdx.x; n < N;
             n += gridDim.x * blockDim.x) {
            int g = batch[n];
            for (int h = 0; h < H; h++) {
                float s = g_s[(size_t)n * H + h];
                float v = s > 0.0f ? logf(s) : 0.0f;
                atomicAdd(&sred[g * H + h], v);
            }
        }
    }
    __syncthreads();
    float coef = g_coef;
    for (int i = threadIdx.x; i < gh; i += blockDim.x) {
        float v = sred[i];
        if (v != 0.0f) atomicAdd(&out[i], coef * v);
    }
}

// Fallback: direct global atomics (only if out_size > MAX_GH)
__global__ void node_kernel_g(const int* __restrict__ batch,
                              float* __restrict__ out,
                              int N, int H) {
    int n = blockIdx.x * blockDim.x + threadIdx.x;
    if (n >= N) return;
    float coef = g_coef;
    int g = batch[n];
    for (int h = 0; h < H; h++) {
        float s = g_s[(size_t)n * H + h];
        float v = s > 0.0f ? logf(s) : 0.0f;
        atomicAdd(&out[g * H + h], coef * v);
    }
}

// ---------------------------------------------------------------------------
// Launch.  Inputs (metadata order):
//   0: G [4,4] f32 (unused)   1: Q2 [N,H,D] f32   2: K2 [N,H,D] f32
//   3: a_2 [H] f32   4: lambda_2_raw [1] f32   5: beta_2_raw [1] f32
//   6: c_2 [E] i32   7: u_2 [E] i32   8: batch [N] i32
// Output: [num_graphs, H] f32
// ---------------------------------------------------------------------------
extern "C" void kernel_launch(void* const* d_in, const int* in_sizes, int n_in,
                              void* d_out, int out_size) {
    const float* Q        = (const float*)d_in[1];
    const float* K        = (const float*)d_in[2];
    const float* a        = (const float*)d_in[3];
    const float* lam_raw  = (const float*)d_in[4];
    const float* beta_raw = (const float*)d_in[5];
    const int*   c        = (const int*)d_in[6];
    const int*   u        = (const int*)d_in[7];
    const int*   batch    = (const int*)d_in[8];
    float*       out      = (float*)d_out;

    int H = in_sizes[3];
    int E = in_sizes[6];
    int N = in_sizes[8];
    long long nhd = in_sizes[1];
    int D = (int)(nhd / ((long long)N * H));

    int s_count = N * H;
    if (s_count > MAX_S) return;

    const int TB = 256;
    bool fast = (H == 4 && D == 32 && nhd <= MAX_NHD && (nhd % 4) == 0);

    if (fast) {
        int total4 = (int)(nhd / 4);
        int work = total4;
        if (s_count > work) work = s_count;
        if (out_size > work) work = out_size;
        prep_kernel<<<(work + TB - 1) / TB, TB>>>(Q, K, a, lam_raw, beta_raw,
                                                  out, out_size, s_count, total4, H, D);

        // 16 edges per warp
        long long warps = (E + 15) / 16;
        long long threads = warps * 32;
        int blocks = (int)((threads + TB - 1) / TB);
        edge_kernel_16<<<blocks, TB>>>(c, u, E);
    } else {
        prep_kernel<<<((s_count > out_size ? s_count : out_size) + TB - 1) / TB, TB>>>(
            Q, K, a, lam_raw, beta_raw, out, out_size, s_count, 0, H, D);
        long long total = (long long)E * H;
        edge_kernel_g<<<(int)((total + TB - 1) / TB), TB>>>(Q, K, a, beta_raw, c, u, E, H, D);
    }

    if (out_size <= MAX_GH) {
        int blocks = (N + TB - 1) / TB;
        if (blocks > 120) blocks = 120;
        node_kernel_sm<<<blocks, TB>>>(batch, out, N, H, out_size);
    } else {
        node_kernel_g<<<(N + TB - 1) / TB, TB>>>(batch, out, N, H);
    }
}